// round 1
// baseline (speedup 1.0000x reference)
#include <cuda_runtime.h>
#include <math.h>

// Problem constants
#define BB 4
#define SS 2048
#define HH 16
#define DD 64
#define DM 1024
#define MM (BB*SS)   // 8192 rows

// ---------------------------------------------------------------------------
// Scratch (allocation-free: __device__ globals)
// ---------------------------------------------------------------------------
__device__ float g_qh[(size_t)BB*HH*SS*DD];   // (B,H,S,64)
__device__ float g_kh[(size_t)BB*HH*SS*DD];
__device__ float g_vh[(size_t)BB*HH*SS*DD];
__device__ float g_ctx[(size_t)MM*DM];        // (B,S,H*64)
__device__ float g_tmp[(size_t)MM*DM];        // pre-LN output

// ---------------------------------------------------------------------------
// SGEMM: C[m][n] = X[m][:] . W[n][:] + bias[n] (+ res),  K = DM = 1024
// 128x128 block tile, BK=8, 256 threads, 8x8 microtile.
// PROJ=true : write to (B,H,S,64) layout for per-head tensors
// PROJ=false: write row-major (M,DM) with residual add
// ---------------------------------------------------------------------------
template<bool PROJ>
__global__ __launch_bounds__(256)
void sgemm128(const float* __restrict__ X, const float* __restrict__ W,
              const float* __restrict__ bias, const float* __restrict__ res,
              float* __restrict__ out)
{
    const int bm = blockIdx.y * 128;
    const int bn = blockIdx.x * 128;

    __shared__ float As[8][128];
    __shared__ float Bs[8][128];

    const int tid = threadIdx.x;
    const int tx  = tid & 15;     // 0..15
    const int ty  = tid >> 4;     // 0..15
    const int lr  = tid >> 1;     // 0..127
    const int lk  = (tid & 1) * 4;

    float acc[8][8];
    #pragma unroll
    for (int i = 0; i < 8; i++)
        #pragma unroll
        for (int j = 0; j < 8; j++) acc[i][j] = 0.f;

    for (int k0 = 0; k0 < DM; k0 += 8) {
        float4 av = *(const float4*)&X[(size_t)(bm + lr) * DM + k0 + lk];
        float4 bv = *(const float4*)&W[(size_t)(bn + lr) * DM + k0 + lk];
        As[lk+0][lr] = av.x; As[lk+1][lr] = av.y; As[lk+2][lr] = av.z; As[lk+3][lr] = av.w;
        Bs[lk+0][lr] = bv.x; Bs[lk+1][lr] = bv.y; Bs[lk+2][lr] = bv.z; Bs[lk+3][lr] = bv.w;
        __syncthreads();

        #pragma unroll
        for (int k = 0; k < 8; k++) {
            float a[8], b[8];
            *(float4*)&a[0] = *(const float4*)&As[k][ty*8];
            *(float4*)&a[4] = *(const float4*)&As[k][ty*8 + 4];
            *(float4*)&b[0] = *(const float4*)&Bs[k][tx*8];
            *(float4*)&b[4] = *(const float4*)&Bs[k][tx*8 + 4];
            #pragma unroll
            for (int i = 0; i < 8; i++)
                #pragma unroll
                for (int j = 0; j < 8; j++)
                    acc[i][j] += a[i] * b[j];
        }
        __syncthreads();
    }

    #pragma unroll
    for (int i = 0; i < 8; i++) {
        const int m = bm + ty*8 + i;
        #pragma unroll
        for (int jj = 0; jj < 2; jj++) {
            const int n = bn + tx*8 + jj*4;
            float4 o;
            o.x = acc[i][jj*4+0] + bias[n+0];
            o.y = acc[i][jj*4+1] + bias[n+1];
            o.z = acc[i][jj*4+2] + bias[n+2];
            o.w = acc[i][jj*4+3] + bias[n+3];
            if (PROJ) {
                const int b = m >> 11, s = m & 2047;
                const int h = n >> 6, d = n & 63;
                *(float4*)&out[(((size_t)(b*HH + h) * SS + s) * DD + d)] = o;
            } else {
                const float4 r4 = *(const float4*)&res[(size_t)m * DM + n];
                o.x += r4.x; o.y += r4.y; o.z += r4.z; o.w += r4.w;
                *(float4*)&out[(size_t)m * DM + n] = o;
            }
        }
    }
}

// ---------------------------------------------------------------------------
// scores: raw[b,h,q,k] = (qh . kh) / 8   (K=64, 64x64 tile, 4x4 microtile)
// Writes scaled raw scores directly into the attn region of d_out.
// ---------------------------------------------------------------------------
__global__ __launch_bounds__(256)
void scores_kernel(const float* __restrict__ qh, const float* __restrict__ kh,
                   float* __restrict__ attn)
{
    const int bh = blockIdx.z;
    const int m0 = blockIdx.y * 64;
    const int n0 = blockIdx.x * 64;
    const float* A = qh + (size_t)bh * SS * DD;
    const float* B = kh + (size_t)bh * SS * DD;

    __shared__ float As[64][68];   // k-major: As[k][m]
    __shared__ float Bs[64][68];   // k-major: Bs[k][n]

    const int tid = threadIdx.x;
    const int tx  = tid & 15, ty = tid >> 4;

    {
        const int r  = tid >> 4;         // 0..15
        const int c4 = (tid & 15) * 4;   // 0..60
        #pragma unroll
        for (int it = 0; it < 4; it++) {
            const int row = r + it*16;
            float4 av = *(const float4*)&A[(size_t)(m0 + row) * DD + c4];
            float4 bv = *(const float4*)&B[(size_t)(n0 + row) * DD + c4];
            As[c4+0][row] = av.x; As[c4+1][row] = av.y; As[c4+2][row] = av.z; As[c4+3][row] = av.w;
            Bs[c4+0][row] = bv.x; Bs[c4+1][row] = bv.y; Bs[c4+2][row] = bv.z; Bs[c4+3][row] = bv.w;
        }
    }
    __syncthreads();

    float acc[4][4];
    #pragma unroll
    for (int i = 0; i < 4; i++)
        #pragma unroll
        for (int j = 0; j < 4; j++) acc[i][j] = 0.f;

    #pragma unroll 8
    for (int k = 0; k < 64; k++) {
        float4 a4 = *(const float4*)&As[k][ty*4];
        float4 b4 = *(const float4*)&Bs[k][tx*4];
        const float a[4] = {a4.x, a4.y, a4.z, a4.w};
        const float b[4] = {b4.x, b4.y, b4.z, b4.w};
        #pragma unroll
        for (int i = 0; i < 4; i++)
            #pragma unroll
            for (int j = 0; j < 4; j++)
                acc[i][j] += a[i] * b[j];
    }

    #pragma unroll
    for (int i = 0; i < 4; i++) {
        float4 o;
        o.x = acc[i][0] * 0.125f;
        o.y = acc[i][1] * 0.125f;
        o.z = acc[i][2] * 0.125f;
        o.w = acc[i][3] * 0.125f;
        *(float4*)&attn[((size_t)bh * SS + m0 + ty*4 + i) * SS + n0 + tx*4] = o;
    }
}

// ---------------------------------------------------------------------------
// Row softmax in-place over 2048 elements (one block per row)
// ---------------------------------------------------------------------------
__device__ __forceinline__ float blk_sum8(float v, volatile float* sb) {
    const int lane = threadIdx.x & 31, w = threadIdx.x >> 5;
    #pragma unroll
    for (int o = 16; o; o >>= 1) v += __shfl_xor_sync(0xffffffffu, v, o);
    if (!lane) sb[w] = v;
    __syncthreads();
    float r = 0.f;
    #pragma unroll
    for (int i = 0; i < 8; i++) r += sb[i];
    __syncthreads();
    return r;
}

__device__ __forceinline__ float blk_max8(float v, volatile float* sb) {
    const int lane = threadIdx.x & 31, w = threadIdx.x >> 5;
    #pragma unroll
    for (int o = 16; o; o >>= 1) v = fmaxf(v, __shfl_xor_sync(0xffffffffu, v, o));
    if (!lane) sb[w] = v;
    __syncthreads();
    float r = -3.4e38f;
    #pragma unroll
    for (int i = 0; i < 8; i++) r = fmaxf(r, sb[i]);
    __syncthreads();
    return r;
}

__global__ __launch_bounds__(256)
void softmax_kernel(float* __restrict__ attn)
{
    __shared__ float sb[8];
    const size_t row = blockIdx.x;
    float* p = attn + row * (size_t)SS;
    const int t = threadIdx.x;

    float4 v0 = ((float4*)p)[t];
    float4 v1 = ((float4*)p)[t + 256];

    float m = fmaxf(fmaxf(fmaxf(v0.x, v0.y), fmaxf(v0.z, v0.w)),
                    fmaxf(fmaxf(v1.x, v1.y), fmaxf(v1.z, v1.w)));
    m = blk_max8(m, sb);

    v0.x = __expf(v0.x - m); v0.y = __expf(v0.y - m);
    v0.z = __expf(v0.z - m); v0.w = __expf(v0.w - m);
    v1.x = __expf(v1.x - m); v1.y = __expf(v1.y - m);
    v1.z = __expf(v1.z - m); v1.w = __expf(v1.w - m);

    float s = (v0.x + v0.y + v0.z + v0.w) + (v1.x + v1.y + v1.z + v1.w);
    s = blk_sum8(s, sb);
    const float inv = 1.f / s;

    v0.x *= inv; v0.y *= inv; v0.z *= inv; v0.w *= inv;
    v1.x *= inv; v1.y *= inv; v1.z *= inv; v1.w *= inv;

    ((float4*)p)[t]       = v0;
    ((float4*)p)[t + 256] = v1;
}

// ---------------------------------------------------------------------------
// ctx[b,s,h*64+d] = sum_k attn[b,h,s,k] * vh[b,h,k,d]
// 128x64 tile, K-tile 32, 8x4 microtile
// ---------------------------------------------------------------------------
__global__ __launch_bounds__(256)
void ctx_kernel(const float* __restrict__ attn, const float* __restrict__ vh,
                float* __restrict__ ctx)
{
    const int bh = blockIdx.y;
    const int m0 = blockIdx.x * 128;
    const float* A = attn + (size_t)bh * SS * SS;
    const float* V = vh   + (size_t)bh * SS * DD;

    __shared__ float As[32][132];  // k-major: As[k][m]
    __shared__ float Bs[32][64];   // Bs[k][d]

    const int tid = threadIdx.x;
    const int tx  = tid & 15, ty = tid >> 4;

    float acc[8][4];
    #pragma unroll
    for (int i = 0; i < 8; i++)
        #pragma unroll
        for (int j = 0; j < 4; j++) acc[i][j] = 0.f;

    for (int k0 = 0; k0 < SS; k0 += 32) {
        {
            const int r  = tid >> 3;        // 0..31
            const int c4 = (tid & 7) * 4;   // 0..28
            #pragma unroll
            for (int it = 0; it < 4; it++) {
                const int row = r + it*32;
                float4 av = *(const float4*)&A[(size_t)(m0 + row) * SS + k0 + c4];
                As[c4+0][row] = av.x; As[c4+1][row] = av.y;
                As[c4+2][row] = av.z; As[c4+3][row] = av.w;
            }
            const int vr  = tid >> 4;        // 0..15
            const int vc4 = (tid & 15) * 4;  // 0..60
            #pragma unroll
            for (int it = 0; it < 2; it++)
                *(float4*)&Bs[vr + it*16][vc4] =
                    *(const float4*)&V[(size_t)(k0 + vr + it*16) * DD + vc4];
        }
        __syncthreads();

        #pragma unroll 8
        for (int k = 0; k < 32; k++) {
            float a[8];
            *(float4*)&a[0] = *(const float4*)&As[k][ty*8];
            *(float4*)&a[4] = *(const float4*)&As[k][ty*8 + 4];
            float4 b4 = *(const float4*)&Bs[k][tx*4];
            const float b[4] = {b4.x, b4.y, b4.z, b4.w};
            #pragma unroll
            for (int i = 0; i < 8; i++)
                #pragma unroll
                for (int j = 0; j < 4; j++)
                    acc[i][j] += a[i] * b[j];
        }
        __syncthreads();
    }

    const int b = bh / HH, h = bh % HH;
    #pragma unroll
    for (int i = 0; i < 8; i++) {
        const int m = m0 + ty*8 + i;
        float4 o = make_float4(acc[i][0], acc[i][1], acc[i][2], acc[i][3]);
        *(float4*)&ctx[((size_t)(b * SS + m)) * DM + h*DD + tx*4] = o;
    }
}

// ---------------------------------------------------------------------------
// LayerNorm over last dim (1024), eps=1e-6
// ---------------------------------------------------------------------------
__global__ __launch_bounds__(256)
void ln_kernel(const float* __restrict__ xin, const float* __restrict__ gamma,
               const float* __restrict__ beta, float* __restrict__ out)
{
    __shared__ float sb[8];
    const size_t row = blockIdx.x;
    const float* x = xin + row * DM;
    const int t = threadIdx.x;

    float4 v = ((const float4*)x)[t];
    float s = v.x + v.y + v.z + v.w;
    s = blk_sum8(s, sb);
    const float mu = s * (1.f / 1024.f);

    const float dx = v.x - mu, dy = v.y - mu, dz = v.z - mu, dw = v.w - mu;
    float sq = dx*dx + dy*dy + dz*dz + dw*dw;
    sq = blk_sum8(sq, sb);
    const float rstd = rsqrtf(sq * (1.f / 1024.f) + 1e-6f);

    const float4 g  = ((const float4*)gamma)[t];
    const float4 be = ((const float4*)beta)[t];
    float4 o;
    o.x = dx * rstd * g.x + be.x;
    o.y = dy * rstd * g.y + be.y;
    o.z = dz * rstd * g.z + be.z;
    o.w = dw * rstd * g.w + be.w;
    ((float4*)(out + row * DM))[t] = o;
}

// ---------------------------------------------------------------------------
// Launch
// ---------------------------------------------------------------------------
extern "C" void kernel_launch(void* const* d_in, const int* in_sizes, int n_in,
                              void* d_out, int out_size)
{
    const float* q     = (const float*)d_in[0];
    const float* k     = (const float*)d_in[1];
    const float* v     = (const float*)d_in[2];
    const float* Wq    = (const float*)d_in[3];
    const float* bq    = (const float*)d_in[4];
    const float* Wk    = (const float*)d_in[5];
    const float* bk    = (const float*)d_in[6];
    const float* Wv    = (const float*)d_in[7];
    const float* bv    = (const float*)d_in[8];
    const float* Wo    = (const float*)d_in[9];
    const float* bo    = (const float*)d_in[10];
    const float* gamma = (const float*)d_in[11];
    const float* beta  = (const float*)d_in[12];

    float* out  = (float*)d_out;                  // (B,S,D) = 8,388,608 floats
    float* attn = out + (size_t)MM * DM;          // (B,H,S,S) follows in tuple order

    float *qh, *kh, *vh, *ctx, *tmp;
    cudaGetSymbolAddress((void**)&qh,  g_qh);
    cudaGetSymbolAddress((void**)&kh,  g_kh);
    cudaGetSymbolAddress((void**)&vh,  g_vh);
    cudaGetSymbolAddress((void**)&ctx, g_ctx);
    cudaGetSymbolAddress((void**)&tmp, g_tmp);

    const dim3 g1(DM / 128, MM / 128);   // (8, 64)

    // QKV projections -> (B,H,S,64)
    sgemm128<true><<<g1, 256>>>(q, Wq, bq, nullptr, qh);
    sgemm128<true><<<g1, 256>>>(k, Wk, bk, nullptr, kh);
    sgemm128<true><<<g1, 256>>>(v, Wv, bv, nullptr, vh);

    // scores (scaled) -> attn region of d_out
    scores_kernel<<<dim3(SS / 64, SS / 64, BB * HH), 256>>>(qh, kh, attn);

    // softmax in place
    softmax_kernel<<<BB * HH * SS, 256>>>(attn);

    // ctx = attn @ vh -> (B,S,H*64)
    ctx_kernel<<<dim3(SS / 128, BB * HH), 256>>>(attn, vh, ctx);

    // out-proj + bias + residual -> tmp (row-major)
    sgemm128<false><<<g1, 256>>>(ctx, Wo, bo, q, tmp);

    // LayerNorm -> out region of d_out
    ln_kernel<<<MM, 256>>>(tmp, gamma, beta, out);
}

// round 2
// speedup vs baseline: 3.4626x; 3.4626x over previous
#include <cuda_runtime.h>
#include <cuda_fp16.h>
#include <mma.h>
#include <math.h>

using namespace nvcuda;

#define BB 4
#define SS 2048
#define HH 16
#define DD 64
#define DM 1024
#define MM (BB*SS)   // 8192

// ---------------------------------------------------------------------------
// Scratch (__device__ globals; allocation-free)
// ---------------------------------------------------------------------------
__device__ __half g_qx[(size_t)MM*DM];          // fp16 copies of inputs
__device__ __half g_kx[(size_t)MM*DM];
__device__ __half g_vx[(size_t)MM*DM];
__device__ __half g_Wq[(size_t)DM*DM];
__device__ __half g_Wk[(size_t)DM*DM];
__device__ __half g_Wv[(size_t)DM*DM];
__device__ __half g_Wo[(size_t)DM*DM];
__device__ __half g_qh[(size_t)MM*DM];          // (B,H,S,64) fp16
__device__ __half g_kh[(size_t)MM*DM];
__device__ __half g_vh[(size_t)MM*DM];
__device__ __half g_attn[(size_t)BB*HH*SS*SS];  // raw scores -> probs (fp16)
__device__ __half g_ctxh[(size_t)MM*DM];        // ctx fp16 (B,S,H*64)
__device__ float  g_tmp[(size_t)MM*DM];         // pre-LN fp32

struct alignas(8) H4 { __half2 a, b; };

// ---------------------------------------------------------------------------
// fp32 -> fp16 conversion (8 elems / thread)
// ---------------------------------------------------------------------------
__global__ void f2h_kernel(const float* __restrict__ src, __half* __restrict__ dst, int n8)
{
    int i = blockIdx.x * blockDim.x + threadIdx.x;
    if (i >= n8) return;
    float4 a = ((const float4*)src)[2*i];
    float4 b = ((const float4*)src)[2*i+1];
    __half2 h[4];
    h[0] = __floats2half2_rn(a.x, a.y);
    h[1] = __floats2half2_rn(a.z, a.w);
    h[2] = __floats2half2_rn(b.x, b.y);
    h[3] = __floats2half2_rn(b.z, b.w);
    ((uint4*)dst)[i] = *(uint4*)h;
}

// ---------------------------------------------------------------------------
// HGEMM: C[m][n] = A[m][:] . W[n][:] + bias[n] (+res),  A,W fp16, acc fp32
// 128x128 tile, BK=32, 256 threads = 8 warps (4m x 2n), warp tile 32x64.
// K = 1024.  EPI 0: write fp16 to (B,H,S,64).  EPI 1: +residual, write fp32.
// ---------------------------------------------------------------------------
template<int EPI>
__global__ __launch_bounds__(256, 2)
void hgemm128(const __half* __restrict__ A, const __half* __restrict__ Bw,
              const float* __restrict__ bias, const float* __restrict__ res,
              void* __restrict__ out)
{
    extern __shared__ char smem[];
    __half (*As)[40]  = (__half(*)[40])smem;
    __half (*Bs)[40]  = (__half(*)[40])(smem + 128*40*sizeof(__half));
    float  (*Cs)[132] = (float(*)[132])smem;

    const int bm = blockIdx.y * 128;
    const int bn = blockIdx.x * 128;
    const int tid = threadIdx.x, wid = tid >> 5;
    const int wm = (wid & 3) * 32, wn = (wid >> 2) * 64;

    wmma::fragment<wmma::accumulator, 16,16,16, float> acc[2][4];
    #pragma unroll
    for (int i = 0; i < 2; i++)
        #pragma unroll
        for (int j = 0; j < 4; j++) wmma::fill_fragment(acc[i][j], 0.f);

    for (int k0 = 0; k0 < DM; k0 += 32) {
        #pragma unroll
        for (int i = 0; i < 2; i++) {
            int t = i*256 + tid;            // 0..511
            int row = t >> 2, c8 = (t & 3) * 8;
            *(int4*)&As[row][c8] = *(const int4*)&A [(size_t)(bm+row)*DM + k0 + c8];
            *(int4*)&Bs[row][c8] = *(const int4*)&Bw[(size_t)(bn+row)*DM + k0 + c8];
        }
        __syncthreads();

        #pragma unroll
        for (int kk = 0; kk < 32; kk += 16) {
            wmma::fragment<wmma::matrix_a, 16,16,16, __half, wmma::row_major> af[2];
            wmma::fragment<wmma::matrix_b, 16,16,16, __half, wmma::col_major> bf[4];
            #pragma unroll
            for (int i = 0; i < 2; i++)
                wmma::load_matrix_sync(af[i], &As[wm + i*16][kk], 40);
            #pragma unroll
            for (int j = 0; j < 4; j++)
                wmma::load_matrix_sync(bf[j], &Bs[wn + j*16][kk], 40);
            #pragma unroll
            for (int i = 0; i < 2; i++)
                #pragma unroll
                for (int j = 0; j < 4; j++)
                    wmma::mma_sync(acc[i][j], af[i], bf[j], acc[i][j]);
        }
        __syncthreads();
    }

    // Stage accumulators through smem (aliased, safe after sync)
    #pragma unroll
    for (int i = 0; i < 2; i++)
        #pragma unroll
        for (int j = 0; j < 4; j++)
            wmma::store_matrix_sync(&Cs[wm + i*16][wn + j*16], acc[i][j], 132, wmma::mem_row_major);
    __syncthreads();

    #pragma unroll
    for (int it = 0; it < 16; it++) {
        int idx = it*256 + tid;
        int row = idx >> 5, c4 = (idx & 31) * 4;
        int m = bm + row, n = bn + c4;
        float4 c = *(float4*)&Cs[row][c4];
        c.x += bias[n]; c.y += bias[n+1]; c.z += bias[n+2]; c.w += bias[n+3];
        if (EPI == 0) {
            int b = m >> 11, s = m & 2047, h = n >> 6, d = n & 63;
            H4 h4; h4.a = __floats2half2_rn(c.x, c.y); h4.b = __floats2half2_rn(c.z, c.w);
            *(H4*)&((__half*)out)[(((size_t)(b*HH + h) * SS + s) * DD + d)] = h4;
        } else {
            float4 r = *(const float4*)&res[(size_t)m*DM + n];
            c.x += r.x; c.y += r.y; c.z += r.z; c.w += r.w;
            *(float4*)&((float*)out)[(size_t)m*DM + n] = c;
        }
    }
}

// ---------------------------------------------------------------------------
// scores: raw[b,h,q,k] = (qh . kh)/8  -> fp16, K=64, 128x128 tile
// ---------------------------------------------------------------------------
__global__ __launch_bounds__(256, 2)
void hgemm_scores(const __half* __restrict__ qh, const __half* __restrict__ kh,
                  __half* __restrict__ attn)
{
    extern __shared__ char smem[];
    __half (*As)[72]  = (__half(*)[72])smem;
    __half (*Bs)[72]  = (__half(*)[72])(smem + 128*72*sizeof(__half));
    float  (*Cs)[132] = (float(*)[132])smem;

    const int bh = blockIdx.z;
    const int bm = blockIdx.y * 128, bn = blockIdx.x * 128;
    const __half* A = qh + (size_t)bh * SS * DD;
    const __half* B = kh + (size_t)bh * SS * DD;
    const int tid = threadIdx.x, wid = tid >> 5;
    const int wm = (wid & 3) * 32, wn = (wid >> 2) * 64;

    #pragma unroll
    for (int i = 0; i < 4; i++) {
        int t = i*256 + tid;                // 0..1023
        int row = t >> 3, c8 = (t & 7) * 8;
        *(int4*)&As[row][c8] = *(const int4*)&A[(size_t)(bm+row)*DD + c8];
        *(int4*)&Bs[row][c8] = *(const int4*)&B[(size_t)(bn+row)*DD + c8];
    }
    __syncthreads();

    wmma::fragment<wmma::accumulator, 16,16,16, float> acc[2][4];
    #pragma unroll
    for (int i = 0; i < 2; i++)
        #pragma unroll
        for (int j = 0; j < 4; j++) wmma::fill_fragment(acc[i][j], 0.f);

    #pragma unroll
    for (int kk = 0; kk < 64; kk += 16) {
        wmma::fragment<wmma::matrix_a, 16,16,16, __half, wmma::row_major> af[2];
        wmma::fragment<wmma::matrix_b, 16,16,16, __half, wmma::col_major> bf[4];
        #pragma unroll
        for (int i = 0; i < 2; i++)
            wmma::load_matrix_sync(af[i], &As[wm + i*16][kk], 72);
        #pragma unroll
        for (int j = 0; j < 4; j++)
            wmma::load_matrix_sync(bf[j], &Bs[wn + j*16][kk], 72);
        #pragma unroll
        for (int i = 0; i < 2; i++)
            #pragma unroll
            for (int j = 0; j < 4; j++)
                wmma::mma_sync(acc[i][j], af[i], bf[j], acc[i][j]);
    }
    __syncthreads();

    #pragma unroll
    for (int i = 0; i < 2; i++)
        #pragma unroll
        for (int j = 0; j < 4; j++)
            wmma::store_matrix_sync(&Cs[wm + i*16][wn + j*16], acc[i][j], 132, wmma::mem_row_major);
    __syncthreads();

    #pragma unroll
    for (int it = 0; it < 16; it++) {
        int idx = it*256 + tid;
        int row = idx >> 5, c4 = (idx & 31) * 4;
        float4 c = *(float4*)&Cs[row][c4];
        H4 h4;
        h4.a = __floats2half2_rn(c.x * 0.125f, c.y * 0.125f);
        h4.b = __floats2half2_rn(c.z * 0.125f, c.w * 0.125f);
        *(H4*)&attn[((size_t)bh*SS + bm + row) * SS + bn + c4] = h4;
    }
}

// ---------------------------------------------------------------------------
// Block reductions
// ---------------------------------------------------------------------------
__device__ __forceinline__ float blk_sum8(float v, volatile float* sb) {
    const int lane = threadIdx.x & 31, w = threadIdx.x >> 5;
    #pragma unroll
    for (int o = 16; o; o >>= 1) v += __shfl_xor_sync(0xffffffffu, v, o);
    if (!lane) sb[w] = v;
    __syncthreads();
    float r = 0.f;
    #pragma unroll
    for (int i = 0; i < 8; i++) r += sb[i];
    __syncthreads();
    return r;
}
__device__ __forceinline__ float blk_max8(float v, volatile float* sb) {
    const int lane = threadIdx.x & 31, w = threadIdx.x >> 5;
    #pragma unroll
    for (int o = 16; o; o >>= 1) v = fmaxf(v, __shfl_xor_sync(0xffffffffu, v, o));
    if (!lane) sb[w] = v;
    __syncthreads();
    float r = -3.4e38f;
    #pragma unroll
    for (int i = 0; i < 8; i++) r = fmaxf(r, sb[i]);
    __syncthreads();
    return r;
}

// ---------------------------------------------------------------------------
// Softmax: read fp16 raw scores, write fp32 probs (d_out) + fp16 probs (in place)
// ---------------------------------------------------------------------------
__global__ __launch_bounds__(256)
void softmax_kernel(__half* __restrict__ attn, float* __restrict__ attn_out)
{
    __shared__ float sb[8];
    const size_t row = blockIdx.x;
    __half* p  = attn + row * (size_t)SS;
    float* po  = attn_out + row * (size_t)SS;
    const int t = threadIdx.x;

    uint4 u = ((const uint4*)p)[t];
    __half2* h2 = (__half2*)&u;
    float f[8];
    #pragma unroll
    for (int j = 0; j < 4; j++) {
        float2 v = __half22float2(h2[j]);
        f[2*j] = v.x; f[2*j+1] = v.y;
    }

    float m = f[0];
    #pragma unroll
    for (int j = 1; j < 8; j++) m = fmaxf(m, f[j]);
    m = blk_max8(m, sb);

    float s = 0.f;
    #pragma unroll
    for (int j = 0; j < 8; j++) { f[j] = __expf(f[j] - m); s += f[j]; }
    s = blk_sum8(s, sb);
    const float inv = 1.f / s;
    #pragma unroll
    for (int j = 0; j < 8; j++) f[j] *= inv;

    ((float4*)po)[2*t]   = make_float4(f[0], f[1], f[2], f[3]);
    ((float4*)po)[2*t+1] = make_float4(f[4], f[5], f[6], f[7]);

    #pragma unroll
    for (int j = 0; j < 4; j++) h2[j] = __floats2half2_rn(f[2*j], f[2*j+1]);
    ((uint4*)p)[t] = u;
}

// ---------------------------------------------------------------------------
// ctx = attn_probs(fp16) @ vh(fp16): M=2048/bh, N=64, K=2048
// 128x64 tile, BK=32, 8 warps (4m x 2n), warp tile 32x32
// ---------------------------------------------------------------------------
__global__ __launch_bounds__(256, 2)
void hgemm_ctx(const __half* __restrict__ attn, const __half* __restrict__ vh,
               __half* __restrict__ ctx)
{
    extern __shared__ char smem[];
    __half (*As)[40] = (__half(*)[40])smem;                       // 128 x 32(+8)
    __half (*Bs)[72] = (__half(*)[72])(smem + 128*40*sizeof(__half)); // 32 x 64(+8)
    float  (*Cs)[68] = (float(*)[68])smem;

    const int bh = blockIdx.y;
    const int bm = blockIdx.x * 128;
    const __half* A = attn + (size_t)bh * SS * SS;
    const __half* V = vh   + (size_t)bh * SS * DD;
    const int tid = threadIdx.x, wid = tid >> 5;
    const int wm = (wid & 3) * 32, wn = (wid >> 2) * 32;

    wmma::fragment<wmma::accumulator, 16,16,16, float> acc[2][2];
    #pragma unroll
    for (int i = 0; i < 2; i++)
        #pragma unroll
        for (int j = 0; j < 2; j++) wmma::fill_fragment(acc[i][j], 0.f);

    for (int k0 = 0; k0 < SS; k0 += 32) {
        #pragma unroll
        for (int i = 0; i < 2; i++) {
            int t = i*256 + tid;
            int row = t >> 2, c8 = (t & 3) * 8;
            *(int4*)&As[row][c8] = *(const int4*)&A[(size_t)(bm+row)*SS + k0 + c8];
        }
        {
            int r = tid >> 3, c8 = (tid & 7) * 8;
            *(int4*)&Bs[r][c8] = *(const int4*)&V[(size_t)(k0+r)*DD + c8];
        }
        __syncthreads();

        #pragma unroll
        for (int kk = 0; kk < 32; kk += 16) {
            wmma::fragment<wmma::matrix_a, 16,16,16, __half, wmma::row_major> af[2];
            wmma::fragment<wmma::matrix_b, 16,16,16, __half, wmma::row_major> bf[2];
            #pragma unroll
            for (int i = 0; i < 2; i++)
                wmma::load_matrix_sync(af[i], &As[wm + i*16][kk], 40);
            #pragma unroll
            for (int j = 0; j < 2; j++)
                wmma::load_matrix_sync(bf[j], &Bs[kk][wn + j*16], 72);
            #pragma unroll
            for (int i = 0; i < 2; i++)
                #pragma unroll
                for (int j = 0; j < 2; j++)
                    wmma::mma_sync(acc[i][j], af[i], bf[j], acc[i][j]);
        }
        __syncthreads();
    }

    #pragma unroll
    for (int i = 0; i < 2; i++)
        #pragma unroll
        for (int j = 0; j < 2; j++)
            wmma::store_matrix_sync(&Cs[wm + i*16][wn + j*16], acc[i][j], 68, wmma::mem_row_major);
    __syncthreads();

    const int b = bh / HH, h = bh % HH;
    #pragma unroll
    for (int it = 0; it < 8; it++) {
        int idx = it*256 + tid;
        int row = idx >> 4, c4 = (idx & 15) * 4;
        int m = bm + row;
        float4 c = *(float4*)&Cs[row][c4];
        H4 h4; h4.a = __floats2half2_rn(c.x, c.y); h4.b = __floats2half2_rn(c.z, c.w);
        *(H4*)&ctx[((size_t)(b*SS + m)) * DM + h*DD + c4] = h4;
    }
}

// ---------------------------------------------------------------------------
// LayerNorm over last dim (1024), eps=1e-6
// ---------------------------------------------------------------------------
__global__ __launch_bounds__(256)
void ln_kernel(const float* __restrict__ xin, const float* __restrict__ gamma,
               const float* __restrict__ beta, float* __restrict__ out)
{
    __shared__ float sb[8];
    const size_t row = blockIdx.x;
    const float* x = xin + row * DM;
    const int t = threadIdx.x;

    float4 v = ((const float4*)x)[t];
    float s = v.x + v.y + v.z + v.w;
    s = blk_sum8(s, sb);
    const float mu = s * (1.f / 1024.f);

    const float dx = v.x - mu, dy = v.y - mu, dz = v.z - mu, dw = v.w - mu;
    float sq = dx*dx + dy*dy + dz*dz + dw*dw;
    sq = blk_sum8(sq, sb);
    const float rstd = rsqrtf(sq * (1.f / 1024.f) + 1e-6f);

    const float4 g  = ((const float4*)gamma)[t];
    const float4 be = ((const float4*)beta)[t];
    float4 o;
    o.x = dx * rstd * g.x + be.x;
    o.y = dy * rstd * g.y + be.y;
    o.z = dz * rstd * g.z + be.z;
    o.w = dw * rstd * g.w + be.w;
    ((float4*)(out + row * DM))[t] = o;
}

// ---------------------------------------------------------------------------
// Launch
// ---------------------------------------------------------------------------
extern "C" void kernel_launch(void* const* d_in, const int* in_sizes, int n_in,
                              void* d_out, int out_size)
{
    const float* q     = (const float*)d_in[0];
    const float* k     = (const float*)d_in[1];
    const float* v     = (const float*)d_in[2];
    const float* Wq    = (const float*)d_in[3];
    const float* bq    = (const float*)d_in[4];
    const float* Wk    = (const float*)d_in[5];
    const float* bk    = (const float*)d_in[6];
    const float* Wv    = (const float*)d_in[7];
    const float* bv    = (const float*)d_in[8];
    const float* Wo    = (const float*)d_in[9];
    const float* bo    = (const float*)d_in[10];
    const float* gamma = (const float*)d_in[11];
    const float* beta  = (const float*)d_in[12];

    float* out      = (float*)d_out;
    float* attn_out = out + (size_t)MM * DM;

    __half *qx, *kx, *vx, *wq, *wk, *wv, *wo, *qh, *kh, *vh, *attn, *ctxh;
    float  *tmp;
    cudaGetSymbolAddress((void**)&qx,   g_qx);
    cudaGetSymbolAddress((void**)&kx,   g_kx);
    cudaGetSymbolAddress((void**)&vx,   g_vx);
    cudaGetSymbolAddress((void**)&wq,   g_Wq);
    cudaGetSymbolAddress((void**)&wk,   g_Wk);
    cudaGetSymbolAddress((void**)&wv,   g_Wv);
    cudaGetSymbolAddress((void**)&wo,   g_Wo);
    cudaGetSymbolAddress((void**)&qh,   g_qh);
    cudaGetSymbolAddress((void**)&kh,   g_kh);
    cudaGetSymbolAddress((void**)&vh,   g_vh);
    cudaGetSymbolAddress((void**)&attn, g_attn);
    cudaGetSymbolAddress((void**)&ctxh, g_ctxh);
    cudaGetSymbolAddress((void**)&tmp,  g_tmp);

    // Opt-in to >48KB dynamic smem (host-side, graph-capture safe)
    const int SM_GEMM = 128*132*4;            // 67584
    cudaFuncSetAttribute(hgemm128<0>,  cudaFuncAttributeMaxDynamicSharedMemorySize, SM_GEMM);
    cudaFuncSetAttribute(hgemm128<1>,  cudaFuncAttributeMaxDynamicSharedMemorySize, SM_GEMM);
    cudaFuncSetAttribute(hgemm_scores, cudaFuncAttributeMaxDynamicSharedMemorySize, SM_GEMM);
    const int SM_CTX = 128*68*4;              // 34816

    // fp32 -> fp16 conversions
    const int n8x = MM*DM/8, n8w = DM*DM/8;
    f2h_kernel<<<(n8x+255)/256, 256>>>(q,  qx, n8x);
    f2h_kernel<<<(n8x+255)/256, 256>>>(k,  kx, n8x);
    f2h_kernel<<<(n8x+255)/256, 256>>>(v,  vx, n8x);
    f2h_kernel<<<(n8w+255)/256, 256>>>(Wq, wq, n8w);
    f2h_kernel<<<(n8w+255)/256, 256>>>(Wk, wk, n8w);
    f2h_kernel<<<(n8w+255)/256, 256>>>(Wv, wv, n8w);
    f2h_kernel<<<(n8w+255)/256, 256>>>(Wo, wo, n8w);

    const dim3 g1(DM/128, MM/128);   // (8, 64)

    // QKV projections -> (B,H,S,64) fp16
    hgemm128<0><<<g1, 256, SM_GEMM>>>(qx, wq, bq, nullptr, qh);
    hgemm128<0><<<g1, 256, SM_GEMM>>>(kx, wk, bk, nullptr, kh);
    hgemm128<0><<<g1, 256, SM_GEMM>>>(vx, wv, bv, nullptr, vh);

    // scaled raw scores -> fp16
    hgemm_scores<<<dim3(SS/128, SS/128, BB*HH), 256, SM_GEMM>>>(qh, kh, attn);

    // softmax: fp32 probs -> d_out, fp16 probs in place
    softmax_kernel<<<BB*HH*SS, 256>>>(attn, attn_out);

    // ctx = probs @ vh -> fp16 (B,S,H*64)
    hgemm_ctx<<<dim3(SS/128, BB*HH), 256, SM_CTX>>>(attn, vh, ctxh);

    // out-proj + bias + residual -> fp32 tmp
    hgemm128<1><<<g1, 256, SM_GEMM>>>(ctxh, wo, bo, q, tmp);

    // LayerNorm -> d_out
    ln_kernel<<<MM, 256>>>(tmp, gamma, beta, out);
}